// round 8
// baseline (speedup 1.0000x reference)
#include <cuda_runtime.h>
#include <cuda_bf16.h>
#include <cstdint>

// out[t, d] = code[weight[row, d]] * absmax[row],  row = tokens[t]
// tokens [8192], weight [50400,4096] int32 codes, absmax [50400], code [256].
// Output [8192,4096] fp32. ~134 MB read + ~134 MB write, HBM-bound.
//
// R6 -> R7: the missing clean experiment. R4's one-shot grid (persistent
// grids proven -1.5..-4 us) + 32-way bank-replicated LUT (LDS degree-1
// guaranteed) at FULL occupancy: 512-thr CTAs, 32 KB smem, 4 CTAs/SM =
// 2048 thr/SM. Tests whether LDS conflict replays in the shared LSU pipe
// (24K of 39K busy l1tex cycles/SM) are what hold DRAM at 67%.

static constexpr int DIM = 4096;
static constexpr int THREADS = 512;
static constexpr int VECS = DIM / 4;          // 1024 int4 per row
static constexpr int VPT = VECS / THREADS;    // 2 int4 per thread per token

__global__ __launch_bounds__(THREADS)
void bnb_embed_kernel(const int* __restrict__ tokens,
                      const int* __restrict__ weight,
                      const float* __restrict__ absmax,
                      const float* __restrict__ code,
                      float* __restrict__ out,
                      int n_tokens)
{
    // 32 replicated copies: entry i for lane l at s_code[i*32 + l].
    // bank = (i*32 + l) & 31 = l  -> degree-1 for ANY index pattern.
    __shared__ float s_code[256 * 32];
    const int tid  = threadIdx.x;
    const int lane = tid & 31;
    const int wid  = tid >> 5;                 // 16 warps

    // Fill: warp w covers entries {w, w+16, ...}: 16 conflict-free STS each.
#pragma unroll
    for (int i = 0; i < 16; i++) {
        const int e = wid + i * 16;
        s_code[e * 32 + lane] = code[e];       // broadcast LDG, L1-hot
    }
    __syncthreads();

    const float* __restrict__ my_lut = s_code + lane;

    const int tA = blockIdx.x * 2;
    const int tB = tA + 1;
    const bool hasB = (tB < n_tokens);

    const int rowA = __ldg(&tokens[tA]);
    const int rowB = hasB ? __ldg(&tokens[tB]) : rowA;
    const float scaleA = __ldg(&absmax[rowA]);
    const float scaleB = __ldg(&absmax[rowB]);

    const int4* __restrict__ wA =
        reinterpret_cast<const int4*>(weight + (long long)rowA * DIM);
    const int4* __restrict__ wB =
        reinterpret_cast<const int4*>(weight + (long long)rowB * DIM);
    float4* __restrict__ oA = reinterpret_cast<float4*>(out + (long long)tA * DIM);
    float4* __restrict__ oB = reinterpret_cast<float4*>(out + (long long)tB * DIM);

    // Front-batch all 4 independent 16B loads (two rows in flight).
    int4 qA[VPT], qB[VPT];
#pragma unroll
    for (int i = 0; i < VPT; i++) qA[i] = wA[tid + i * THREADS];
#pragma unroll
    for (int i = 0; i < VPT; i++) qB[i] = wB[tid + i * THREADS];

#pragma unroll
    for (int i = 0; i < VPT; i++) {
        float4 v;
        v.x = my_lut[qA[i].x << 5] * scaleA;
        v.y = my_lut[qA[i].y << 5] * scaleA;
        v.z = my_lut[qA[i].z << 5] * scaleA;
        v.w = my_lut[qA[i].w << 5] * scaleA;
        oA[tid + i * THREADS] = v;
    }
    if (hasB) {
#pragma unroll
        for (int i = 0; i < VPT; i++) {
            float4 v;
            v.x = my_lut[qB[i].x << 5] * scaleB;
            v.y = my_lut[qB[i].y << 5] * scaleB;
            v.z = my_lut[qB[i].z << 5] * scaleB;
            v.w = my_lut[qB[i].w << 5] * scaleB;
            oB[tid + i * THREADS] = v;
        }
    }
}

extern "C" void kernel_launch(void* const* d_in, const int* in_sizes, int n_in,
                              void* d_out, int out_size)
{
    const int*   tokens = (const int*)d_in[0];
    const int*   weight = (const int*)d_in[1];
    const float* absmax = (const float*)d_in[2];
    const float* code   = (const float*)d_in[3];
    float*       out    = (float*)d_out;

    const int n_tokens = in_sizes[0];        // 8192
    const int grid = (n_tokens + 1) / 2;     // 4096 one-shot CTAs
    bnb_embed_kernel<<<grid, THREADS>>>(tokens, weight, absmax, code, out, n_tokens);
}

// round 9
// speedup vs baseline: 1.1249x; 1.1249x over previous
#include <cuda_runtime.h>
#include <cuda_bf16.h>
#include <cstdint>

// out[t, d] = code[weight[row, d]] * absmax[row],  row = tokens[t]
// tokens [8192], weight [50400,4096] int32 codes, absmax [50400], code [256].
// Output [8192,4096] fp32. ~134 MB read + ~134 MB write, HBM-bound.
//
// R7 -> R8: revert replicated LUT for good (triple-confirmed non-binding).
// Attack the per-CTA serial prologue instead: 4 tokens per CTA, all 4 token
// ids fetched in ONE int4 load, 4 absmax loads in parallel -> one dependent
// prologue chain per 4 tokens (R4 paid it per 2). Body streams 4 independent
// rows concurrently in two front-batched load batches (16 data regs, so
// launch_bounds(512,4) keeps full 2048 threads/SM).

static constexpr int DIM = 4096;
static constexpr int THREADS = 512;
static constexpr int TOK = 4;                    // tokens per CTA
static constexpr int VPT = DIM / 4 / THREADS;    // 2 int4 per thread per token

__global__ __launch_bounds__(THREADS, 4)
void bnb_embed_kernel(const int* __restrict__ tokens,
                      const int* __restrict__ weight,
                      const float* __restrict__ absmax,
                      const float* __restrict__ code,
                      float* __restrict__ out,
                      int n_tokens)
{
    __shared__ float s_code[256];
    const int tid = threadIdx.x;
    if (tid < 256) s_code[tid] = code[tid];
    __syncthreads();

    const int t0 = blockIdx.x * TOK;

    if (t0 + TOK <= n_tokens) {
        // One 16B load fetches all 4 token ids (t0 is 4-aligned).
        const int4 tok = *reinterpret_cast<const int4*>(tokens + t0);
        int rows[TOK] = { tok.x, tok.y, tok.z, tok.w };

        float scale[TOK];
#pragma unroll
        for (int r = 0; r < TOK; r++)
            scale[r] = __ldg(&absmax[rows[r]]);   // 4 parallel loads

#pragma unroll
        for (int i = 0; i < VPT; i++) {
            const int idx = tid + i * THREADS;
            // Front-batch 4 independent row loads.
            int4 q[TOK];
#pragma unroll
            for (int r = 0; r < TOK; r++) {
                const int4* wrow = reinterpret_cast<const int4*>(
                    weight + (long long)rows[r] * DIM);
                q[r] = wrow[idx];
            }
#pragma unroll
            for (int r = 0; r < TOK; r++) {
                float4 v;
                v.x = s_code[q[r].x] * scale[r];
                v.y = s_code[q[r].y] * scale[r];
                v.z = s_code[q[r].z] * scale[r];
                v.w = s_code[q[r].w] * scale[r];
                float4* orow = reinterpret_cast<float4*>(
                    out + (long long)(t0 + r) * DIM);
                orow[idx] = v;
            }
        }
    } else {
        // Tail: per-token fallback (unused when n_tokens % 4 == 0).
        for (int t = t0; t < n_tokens; t++) {
            const int row = __ldg(&tokens[t]);
            const float scale = __ldg(&absmax[row]);
            const int4* wrow =
                reinterpret_cast<const int4*>(weight + (long long)row * DIM);
            float4* orow = reinterpret_cast<float4*>(out + (long long)t * DIM);
#pragma unroll
            for (int i = 0; i < VPT; i++) {
                const int idx = tid + i * THREADS;
                const int4 q = wrow[idx];
                float4 v;
                v.x = s_code[q.x] * scale;
                v.y = s_code[q.y] * scale;
                v.z = s_code[q.z] * scale;
                v.w = s_code[q.w] * scale;
                orow[idx] = v;
            }
        }
    }
}

extern "C" void kernel_launch(void* const* d_in, const int* in_sizes, int n_in,
                              void* d_out, int out_size)
{
    const int*   tokens = (const int*)d_in[0];
    const int*   weight = (const int*)d_in[1];
    const float* absmax = (const float*)d_in[2];
    const float* code   = (const float*)d_in[3];
    float*       out    = (float*)d_out;

    const int n_tokens = in_sizes[0];              // 8192
    const int grid = (n_tokens + TOK - 1) / TOK;   // 2048 one-shot CTAs
    bnb_embed_kernel<<<grid, THREADS>>>(tokens, weight, absmax, code, out, n_tokens);
}

// round 10
// speedup vs baseline: 1.1571x; 1.0286x over previous
#include <cuda_runtime.h>
#include <cuda_bf16.h>
#include <cstdint>

// out[t, d] = code[weight[row, d]] * absmax[row],  row = tokens[t]
// tokens [8192], weight [50400,4096] int32 codes, absmax [50400], code [256].
// Output [8192,4096] fp32. ~134 MB read + ~134 MB write, HBM-bound.
//
// R8 -> R9: converged-model micro-variant. Champion R4 structure (one-shot
// CTAs, 2 tokens / 2 independent chains, 4-deep front-batch, default cache,
// plain 1 KB LUT) at 256 threads -> 8 CTAs/SM: twice the independent CTA
// streams per SM to overlap prologue chains and store tails.

static constexpr int DIM = 4096;
static constexpr int THREADS = 256;
static constexpr int VPT = DIM / 4 / THREADS / 2;   // 2 int4 per thread per token

__global__ __launch_bounds__(THREADS, 8)
void bnb_embed_kernel(const int* __restrict__ tokens,
                      const int* __restrict__ weight,
                      const float* __restrict__ absmax,
                      const float* __restrict__ code,
                      float* __restrict__ out,
                      int n_tokens)
{
    __shared__ float s_code[256];
    const int tid = threadIdx.x;
    s_code[tid] = code[tid];
    __syncthreads();

    const int tA = blockIdx.x * 2;
    const int tB = tA + 1;
    const bool hasB = (tB < n_tokens);

    const int rowA = __ldg(&tokens[tA]);
    const int rowB = hasB ? __ldg(&tokens[tB]) : rowA;
    const float scaleA = __ldg(&absmax[rowA]);
    const float scaleB = __ldg(&absmax[rowB]);

    // Each CTA covers the FIRST half of row A and row B? No -- full rows:
    // 256 thr x 2 int4 x 2 iter... VPT=2 here covers half; use stride loop
    // over the two halves to keep regs low while retaining 4-deep batches.
    const int4* __restrict__ wA =
        reinterpret_cast<const int4*>(weight + (long long)rowA * DIM);
    const int4* __restrict__ wB =
        reinterpret_cast<const int4*>(weight + (long long)rowB * DIM);
    float4* __restrict__ oA = reinterpret_cast<float4*>(out + (long long)tA * DIM);
    float4* __restrict__ oB = reinterpret_cast<float4*>(out + (long long)tB * DIM);

#pragma unroll
    for (int h = 0; h < 2; h++) {                 // two halves of the row
        const int base = h * (2 * THREADS);
        // Front-batch 4 independent 16B loads (2 per row, 2 rows).
        int4 qA[VPT], qB[VPT];
#pragma unroll
        for (int i = 0; i < VPT; i++) qA[i] = wA[base + tid + i * THREADS];
#pragma unroll
        for (int i = 0; i < VPT; i++) qB[i] = wB[base + tid + i * THREADS];

#pragma unroll
        for (int i = 0; i < VPT; i++) {
            float4 v;
            v.x = s_code[qA[i].x] * scaleA;
            v.y = s_code[qA[i].y] * scaleA;
            v.z = s_code[qA[i].z] * scaleA;
            v.w = s_code[qA[i].w] * scaleA;
            oA[base + tid + i * THREADS] = v;
        }
        if (hasB) {
#pragma unroll
            for (int i = 0; i < VPT; i++) {
                float4 v;
                v.x = s_code[qB[i].x] * scaleB;
                v.y = s_code[qB[i].y] * scaleB;
                v.z = s_code[qB[i].z] * scaleB;
                v.w = s_code[qB[i].w] * scaleB;
                oB[base + tid + i * THREADS] = v;
            }
        }
    }
}

extern "C" void kernel_launch(void* const* d_in, const int* in_sizes, int n_in,
                              void* d_out, int out_size)
{
    const int*   tokens = (const int*)d_in[0];
    const int*   weight = (const int*)d_in[1];
    const float* absmax = (const float*)d_in[2];
    const float* code   = (const float*)d_in[3];
    float*       out    = (float*)d_out;

    const int n_tokens = in_sizes[0];        // 8192
    const int grid = (n_tokens + 1) / 2;     // 4096 one-shot CTAs
    bnb_embed_kernel<<<grid, THREADS>>>(tokens, weight, absmax, code, out, n_tokens);
}

// round 12
// speedup vs baseline: 1.1653x; 1.0070x over previous
#include <cuda_runtime.h>
#include <cuda_bf16.h>
#include <cstdint>

// out[t, d] = code[weight[row, d]] * absmax[row],  row = tokens[t]
// tokens [8192], weight [50400,4096] int32 codes, absmax [50400], code [256].
// Output [8192,4096] fp32. 268 MB logical traffic; measured effective
// goodput ~6.8 TB/s (L2 absorbs part of the write stream) = converged
// mixed-R/W memory ceiling across 9 structural variants.
//
// FINAL: R1 grid shape (one token per 256-thr one-shot CTA, best bench) +
// R4's explicit 4-deep front-batched loads (best kernel dur). Plain 1 KB
// LUT, default cache policy -- every alternative measured worse:
//   - persistent grids:        +1.5..4 us (R2, R5)
//   - .cs / .cg cache hints:   +1.5 / neutral (R2, R6)
//   - bank-replicated LUT:     +5..13 us (R3, R5, R7; conflicts overlapped)
//   - 2-4 tokens per CTA:      neutral (R4, R8, R9)

static constexpr int DIM = 4096;
static constexpr int THREADS = 256;
static constexpr int VPT = DIM / 4 / THREADS;   // 4 int4 per thread

__global__ __launch_bounds__(THREADS, 8)
void bnb_embed_kernel(const int* __restrict__ tokens,
                      const int* __restrict__ weight,
                      const float* __restrict__ absmax,
                      const float* __restrict__ code,
                      float* __restrict__ out)
{
    __shared__ float s_code[256];
    const int tid = threadIdx.x;
    s_code[tid] = code[tid];
    __syncthreads();

    const int t = blockIdx.x;
    const int row = __ldg(&tokens[t]);
    const float scale = __ldg(&absmax[row]);

    const int4* __restrict__ wrow =
        reinterpret_cast<const int4*>(weight + (long long)row * DIM);
    float4* __restrict__ orow =
        reinterpret_cast<float4*>(out + (long long)t * DIM);

    // Front-batch all 4 independent 16B loads before any LUT work.
    int4 q[VPT];
#pragma unroll
    for (int i = 0; i < VPT; i++)
        q[i] = wrow[tid + i * THREADS];

#pragma unroll
    for (int i = 0; i < VPT; i++) {
        float4 v;
        v.x = s_code[q[i].x] * scale;
        v.y = s_code[q[i].y] * scale;
        v.z = s_code[q[i].z] * scale;
        v.w = s_code[q[i].w] * scale;
        orow[tid + i * THREADS] = v;
    }
}

extern "C" void kernel_launch(void* const* d_in, const int* in_sizes, int n_in,
                              void* d_out, int out_size)
{
    const int*   tokens = (const int*)d_in[0];
    const int*   weight = (const int*)d_in[1];
    const float* absmax = (const float*)d_in[2];
    const float* code   = (const float*)d_in[3];
    float*       out    = (float*)d_out;

    const int n_tokens = in_sizes[0];   // 8192 one-shot CTAs, one per token
    bnb_embed_kernel<<<n_tokens, THREADS>>>(tokens, weight, absmax, code, out);
}